// round 7
// baseline (speedup 1.0000x reference)
#include <cuda_runtime.h>
#include <cuda_bf16.h>
#include <cstdint>
#include <cstddef>

// Problem constants
#define NN 100000      // nodes
#define NE 800000      // edges
#define HD 256         // hidden dim
#define NL 6           // layers
#define W1_LD 259      // H + 3 edge features
#define W2_LD 512      // H + INTER

// ---------------- scratch (device globals; no runtime allocation) ----------
__device__ float g_hA[(size_t)NN * HD];
__device__ float g_hB[(size_t)NN * HD];
__device__ float g_P [(size_t)NN * HD];
__device__ float g_hN[(size_t)NN * HD];
__device__ float g_deg[NN];
__device__ float g_invdeg[NN];

__device__ __forceinline__ float tf32_rna(float a) {
    uint32_t b;
    asm("cvt.rna.tf32.f32 %0, %1;" : "=r"(b) : "f"(a));
    return __uint_as_float(b);
}

__device__ __forceinline__ void mma_tf32(float* c, const float* a, float b0, float b1) {
    asm volatile(
        "mma.sync.aligned.m16n8k8.row.col.f32.tf32.tf32.f32 "
        "{%0,%1,%2,%3}, {%4,%5,%6,%7}, {%8,%9}, {%0,%1,%2,%3};"
        : "+f"(c[0]), "+f"(c[1]), "+f"(c[2]), "+f"(c[3])
        : "r"(__float_as_uint(a[0])), "r"(__float_as_uint(a[1])),
          "r"(__float_as_uint(a[2])), "r"(__float_as_uint(a[3])),
          "r"(__float_as_uint(b0)), "r"(__float_as_uint(b1)));
}

// ---------------- small elementwise kernels --------------------------------
__global__ void init_kernel(const int* __restrict__ gt,
                            const float* __restrict__ emb,
                            float* __restrict__ h,
                            float* __restrict__ deg) {
    int i = blockIdx.x * blockDim.x + threadIdx.x;
    if (i < NN * HD) {
        int node = i >> 8;
        int c    = i & 255;
        h[i] = emb[gt[node] * HD + c];
    }
    if (i < NN) deg[i] = 0.0f;
}

__global__ void deg_kernel(const int* __restrict__ dst, float* __restrict__ deg) {
    int e = blockIdx.x * blockDim.x + threadIdx.x;
    if (e < NE) atomicAdd(&deg[dst[e]], 1.0f);
}

__global__ void invdeg_kernel(const float* __restrict__ deg, float* __restrict__ inv) {
    int i = blockIdx.x * blockDim.x + threadIdx.x;
    if (i < NN) inv[i] = 1.0f / fmaxf(deg[i], 1.0f);
}

__global__ void zero_kernel(float4* __restrict__ p, int n4) {
    int i = blockIdx.x * blockDim.x + threadIdx.x;
    int stride = gridDim.x * blockDim.x;
    float4 z = make_float4(0.f, 0.f, 0.f, 0.f);
    for (; i < n4; i += stride) p[i] = z;
}

// ---------------- edge scatter: hN[dst] += leaky_relu(P[src] + w@W1b^T) ----
// float4 loads + vector reduction (red.global.add.v4.f32)
__global__ void edge_kernel(const int* __restrict__ src,
                            const int* __restrict__ dst,
                            const float* __restrict__ w,
                            const float* __restrict__ P,
                            const float* __restrict__ W1b,  // points at W1[l][0][256]
                            float* __restrict__ hN) {
    __shared__ float sW[3 * HD];   // sW[t*256 + c] = W1[l][c][256+t]
    for (int i = threadIdx.x; i < HD; i += blockDim.x) {
        sW[i]          = W1b[(size_t)i * W1_LD + 0];
        sW[HD + i]     = W1b[(size_t)i * W1_LD + 1];
        sW[2 * HD + i] = W1b[(size_t)i * W1_LD + 2];
    }
    __syncthreads();

    int warpId = (blockIdx.x * blockDim.x + threadIdx.x) >> 5;
    int lane   = threadIdx.x & 31;
    if (warpId >= NE) return;

    int s = src[warpId];
    int d = dst[warpId];
    float w0 = w[warpId * 3 + 0];
    float w1 = w[warpId * 3 + 1];
    float w2 = w[warpId * 3 + 2];

    const float* Ps  = P  + (size_t)s * HD;
    float*       out = hN + (size_t)d * HD;
#pragma unroll
    for (int j = 0; j < 2; j++) {
        int c = j * 128 + lane * 4;
        float4 p = *(const float4*)(Ps + c);
        float4 v;
        v.x = p.x + w0 * sW[c+0] + w1 * sW[HD + c+0] + w2 * sW[2*HD + c+0];
        v.y = p.y + w0 * sW[c+1] + w1 * sW[HD + c+1] + w2 * sW[2*HD + c+1];
        v.z = p.z + w0 * sW[c+2] + w1 * sW[HD + c+2] + w2 * sW[2*HD + c+2];
        v.w = p.w + w0 * sW[c+3] + w1 * sW[HD + c+3] + w2 * sW[2*HD + c+3];
        v.x = v.x > 0.0f ? v.x : 0.01f * v.x;
        v.y = v.y > 0.0f ? v.y : 0.01f * v.y;
        v.z = v.z > 0.0f ? v.z : 0.01f * v.z;
        v.w = v.w > 0.0f ? v.w : 0.01f * v.w;
        asm volatile("red.global.add.v4.f32 [%0], {%1, %2, %3, %4};"
                     :: "l"(out + c), "f"(v.x), "f"(v.y), "f"(v.z), "f"(v.w)
                     : "memory");
    }
}

// ---------------- tensor-core tf32 GEMM (mma.sync, 3-term split) -----------
// C tile 128x64 = act( A1 @ B[:, :K1]^T + (A2*rowscale) @ B[:, K1:]^T + bias )
// Smem holds operands in MMA-FRAGMENT ORDER so each fragment is ONE LDS.128:
//   A: [b16][ks][tg][grp^swz] float4 = {A(r,k), A(r+8,k), A(r,k+4), A(r+8,k+4)}
//   B: [nb ][ks][tg][grp^swz] float4 = {Bhi(k), Bhi(k+4), Blo(k), Blo(k+4)}
// swz = (ks<<2)|tg  (loads conflict-free; stores <=2-way)
#define BM 128
#define BN 64
#define KC 16

__global__ __launch_bounds__(256)
void mma_gemm_kernel(const float* __restrict__ A1, int K1,
                     const float* __restrict__ A2, int K2,
                     const float* __restrict__ rowscale,
                     const float* __restrict__ B, int ldb,
                     const float* __restrict__ bias,
                     float* __restrict__ C, int M, int N, int act) {
    __shared__ float4 AhF[512];   // 8KB
    __shared__ float4 AlF[512];   // 8KB
    __shared__ float4 BF [512];   // 8KB

    int tid  = threadIdx.x;
    int wid  = tid >> 5;
    int lane = tid & 31;
    int grp  = lane >> 2;   // 0..7
    int tg   = lane & 3;    // 0..3
    int warp_m = wid & 3;   // 4 warps along M
    int warp_n = wid >> 2;  // 2 warps along N
    int m0 = warp_m * 32;
    int n0 = warp_n * 32;
    int mBase = blockIdx.y * BM;
    int nBase = blockIdx.x * BN;

    float acc[2][4][4];
#pragma unroll
    for (int i = 0; i < 2; i++)
#pragma unroll
        for (int j = 0; j < 4; j++)
#pragma unroll
            for (int q = 0; q < 4; q++) acc[i][j][q] = 0.0f;

    int K = K1 + K2;
    int nch = K / KC;
    int k1ch = K1 / KC;

    for (int kc = 0; kc < nch; kc++) {
        int kBase = kc * KC;
        bool useA2 = (kc >= k1ch);
        const float* Asrc = useA2 ? A2 : A1;
        int Ak  = useA2 ? (kBase - K1) : kBase;
        int Kld = useA2 ? K2 : K1;

        // A chunk: 128 rows x 16 k = 512 float4 jobs, 2 per thread
#pragma unroll
        for (int i = 0; i < 2; i++) {
            int job = tid + i * 256;
            int r  = job >> 2;          // 0..127
            int c4 = (job & 3) * 4;     // 0,4,8,12
            int row = mBase + r;
            if (row >= M) row = M - 1;
            float4 v = *(const float4*)(Asrc + (size_t)row * Kld + Ak + c4);
            if (useA2) {
                float sc = rowscale[row];
                v.x *= sc; v.y *= sc; v.z *= sc; v.w *= sc;
            }
            float val[4] = {v.x, v.y, v.z, v.w};
            int b16 = r >> 4;
            int rg  = r & 7;
            int up  = (r >> 3) & 1;
#pragma unroll
            for (int d = 0; d < 4; d++) {
                int c = c4 + d;                 // tg = c&3 = d
                int ks = (c >> 3) & 1;
                int second = (c >> 2) & 1;
                int idx = (((b16 * 2 + ks) * 4 + d) << 3) + (rg ^ ((ks << 2) | d));
                float hi = tf32_rna(val[d]);
                float lo = tf32_rna(val[d] - hi);
                ((float*)&AhF[idx])[second * 2 + up] = hi;
                ((float*)&AlF[idx])[second * 2 + up] = lo;
            }
        }
        // B chunk: 64 rows x 16 k = 1024 scalar jobs, 4 per thread (ldb may be odd)
#pragma unroll
        for (int i = 0; i < 4; i++) {
            int job = tid + i * 256;
            int nrow = job >> 4;        // 0..63
            int k = job & 15;
            float v = B[(size_t)(nBase + nrow) * ldb + kBase + k];
            float hi = tf32_rna(v);
            float lo = tf32_rna(v - hi);
            int nb = nrow >> 3;
            int ng = nrow & 7;
            int ks = (k >> 3) & 1;
            int ktg = k & 3;
            int second = (k >> 2) & 1;
            int idx = (((nb * 2 + ks) * 4 + ktg) << 3) + (ng ^ ((ks << 2) | ktg));
            ((float*)&BF[idx])[second] = hi;
            ((float*)&BF[idx])[2 + second] = lo;
        }
        __syncthreads();

#pragma unroll
        for (int ks = 0; ks < 2; ks++) {
            int sw = grp ^ ((ks << 2) | tg);
            float4 ahi[2], alo[2], bfr[4];
#pragma unroll
            for (int mt = 0; mt < 2; mt++) {
                int b16 = (warp_m * 2) + mt;     // (m0 + mt*16) >> 4
                int idx = (((b16 * 2 + ks) * 4 + tg) << 3) + sw;
                ahi[mt] = AhF[idx];
                alo[mt] = AlF[idx];
            }
#pragma unroll
            for (int nt = 0; nt < 4; nt++) {
                int nb = (warp_n * 4) + nt;      // (n0 + nt*8) >> 3
                int idx = (((nb * 2 + ks) * 4 + tg) << 3) + sw;
                bfr[nt] = BF[idx];
            }
#pragma unroll
            for (int mt = 0; mt < 2; mt++)
#pragma unroll
                for (int nt = 0; nt < 4; nt++) {
                    mma_tf32(acc[mt][nt], (float*)&ahi[mt], bfr[nt].x, bfr[nt].y);
                    mma_tf32(acc[mt][nt], (float*)&alo[mt], bfr[nt].x, bfr[nt].y);
                    mma_tf32(acc[mt][nt], (float*)&ahi[mt], bfr[nt].z, bfr[nt].w);
                }
        }
        __syncthreads();
    }

    // Epilogue
#pragma unroll
    for (int mt = 0; mt < 2; mt++) {
#pragma unroll
        for (int half = 0; half < 2; half++) {
            int row = mBase + m0 + mt * 16 + grp + half * 8;
            if (row >= M) continue;
#pragma unroll
            for (int nt = 0; nt < 4; nt++) {
                int col = nBase + n0 + nt * 8 + 2 * tg;
                float2 v;
                v.x = acc[mt][nt][half * 2 + 0];
                v.y = acc[mt][nt][half * 2 + 1];
                if (bias) { v.x += bias[col]; v.y += bias[col + 1]; }
                if (act)  { v.x = fmaxf(v.x, 0.0f); v.y = fmaxf(v.y, 0.0f); }
                *(float2*)(C + (size_t)row * N + col) = v;
            }
        }
    }
}

// ---------------- head dot: out[n] = x[n] . Wh2 + bh2 ----------------------
__global__ void head_dot_kernel(const float* __restrict__ x,
                                const float* __restrict__ Wh2,
                                const float* __restrict__ bh2,
                                float* __restrict__ out) {
    int node = blockIdx.x * (blockDim.x >> 5) + (threadIdx.x >> 5);
    int lane = threadIdx.x & 31;
    if (node >= NN) return;
    const float* xr = x + (size_t)node * HD;
    float s = 0.0f;
#pragma unroll
    for (int j = 0; j < 8; j++) {
        int c = lane + j * 32;
        s = fmaf(xr[c], Wh2[c], s);
    }
#pragma unroll
    for (int off = 16; off; off >>= 1)
        s += __shfl_xor_sync(0xffffffffu, s, off);
    if (lane == 0) out[node] = s + bh2[0];
}

// ---------------- launch ---------------------------------------------------
extern "C" void kernel_launch(void* const* d_in, const int* in_sizes, int n_in,
                              void* d_out, int out_size) {
    const int*   gate_type = (const int*)  d_in[0];
    const int*   src       = (const int*)  d_in[1];
    const int*   dst       = (const int*)  d_in[2];
    const float* w         = (const float*)d_in[3];
    const float* emb       = (const float*)d_in[4];
    const float* W1        = (const float*)d_in[5];
    const float* W2        = (const float*)d_in[6];
    const float* b2        = (const float*)d_in[7];
    const float* Wh1       = (const float*)d_in[8];
    const float* bh1       = (const float*)d_in[9];
    const float* Wh2       = (const float*)d_in[10];
    const float* bh2       = (const float*)d_in[11];
    float* out = (float*)d_out;

    float *hA, *hB, *P, *hN, *deg, *invdeg;
    cudaGetSymbolAddress((void**)&hA,     g_hA);
    cudaGetSymbolAddress((void**)&hB,     g_hB);
    cudaGetSymbolAddress((void**)&P,      g_P);
    cudaGetSymbolAddress((void**)&hN,     g_hN);
    cudaGetSymbolAddress((void**)&deg,    g_deg);
    cudaGetSymbolAddress((void**)&invdeg, g_invdeg);

    // h0 = emb[gate_type]; deg = in-degree; invdeg = 1/max(deg,1)
    init_kernel<<<(NN * HD + 255) / 256, 256>>>(gate_type, emb, hA, deg);
    deg_kernel<<<(NE + 255) / 256, 256>>>(dst, deg);
    invdeg_kernel<<<(NN + 255) / 256, 256>>>(deg, invdeg);

    dim3 ggrid(HD / BN, (NN + BM - 1) / BM);   // (4, 782)
    float* hcur = hA;
    float* hnext = hB;

    for (int l = 0; l < NL; l++) {
        const float* W1l = W1 + (size_t)l * HD * W1_LD;
        const float* W2l = W2 + (size_t)l * HD * W2_LD;
        const float* b2l = b2 + (size_t)l * HD;

        // P = h @ W1[:, :256]^T   (node-space; avoids the 8x larger edge GEMM)
        mma_gemm_kernel<<<ggrid, 256>>>(hcur, HD, nullptr, 0, nullptr,
                                        W1l, W1_LD, nullptr, P, NN, HD, 0);

        zero_kernel<<<2048, 256>>>((float4*)hN, NN * HD / 4);

        // hN[dst] += leaky_relu(P[src] + w @ W1[:, 256:259]^T)
        edge_kernel<<<(NE * 32 + 255) / 256, 256>>>(src, dst, w, P, W1l + HD, hN);

        // h' = relu(h @ W2[:, :256]^T + (hN*invdeg) @ W2[:, 256:]^T + b2)
        mma_gemm_kernel<<<ggrid, 256>>>(hcur, HD, hN, HD, invdeg,
                                        W2l, W2_LD, b2l, hnext, NN, HD, 1);

        float* t = hcur; hcur = hnext; hnext = t;
    }

    // head: x = relu(h @ Wh1^T + bh1); out = x @ Wh2^T + bh2
    mma_gemm_kernel<<<ggrid, 256>>>(hcur, HD, nullptr, 0, nullptr,
                                    Wh1, HD, bh1, P, NN, HD, 1);
    head_dot_kernel<<<(NN * 32 + 255) / 256, 256>>>(P, Wh2, bh2, out);
}

// round 8
// speedup vs baseline: 1.3460x; 1.3460x over previous
#include <cuda_runtime.h>
#include <cuda_bf16.h>
#include <cstdint>
#include <cstddef>

// Problem constants
#define NN 100000      // nodes
#define NE 800000      // edges
#define HD 256         // hidden dim
#define NL 6           // layers
#define W1_LD 259      // H + 3 edge features
#define W2_LD 512      // H + INTER

// ---------------- scratch (device globals; no runtime allocation) ----------
__device__ float g_hA[(size_t)NN * HD];
__device__ float g_hB[(size_t)NN * HD];
__device__ float g_P [(size_t)NN * HD];
__device__ float g_hN[(size_t)NN * HD];
__device__ float g_deg[NN];
__device__ float g_invdeg[NN];

// split a,b into bf16 (hi, lo) packed words: hi word = (bf16(a), bf16(b)),
// lo word = (bf16(a-hi_a), bf16(b-hi_b))
__device__ __forceinline__ void split2(float a, float b, uint32_t& hi, uint32_t& lo) {
    __nv_bfloat16 ha = __float2bfloat16(a);
    __nv_bfloat16 hb = __float2bfloat16(b);
    __nv_bfloat16 la = __float2bfloat16(a - __bfloat162float(ha));
    __nv_bfloat16 lb = __float2bfloat16(b - __bfloat162float(hb));
    __nv_bfloat162 h2 = __halves2bfloat162(ha, hb);
    __nv_bfloat162 l2 = __halves2bfloat162(la, lb);
    hi = *reinterpret_cast<uint32_t*>(&h2);
    lo = *reinterpret_cast<uint32_t*>(&l2);
}

__device__ __forceinline__ void mma_bf16(float* c,
                                         uint32_t a0, uint32_t a1, uint32_t a2, uint32_t a3,
                                         uint32_t b0, uint32_t b1) {
    asm volatile(
        "mma.sync.aligned.m16n8k16.row.col.f32.bf16.bf16.f32 "
        "{%0,%1,%2,%3}, {%4,%5,%6,%7}, {%8,%9}, {%0,%1,%2,%3};"
        : "+f"(c[0]), "+f"(c[1]), "+f"(c[2]), "+f"(c[3])
        : "r"(a0), "r"(a1), "r"(a2), "r"(a3), "r"(b0), "r"(b1));
}

// ---------------- small elementwise kernels --------------------------------
__global__ void init_kernel(const int* __restrict__ gt,
                            const float* __restrict__ emb,
                            float* __restrict__ h,
                            float* __restrict__ deg) {
    int i = blockIdx.x * blockDim.x + threadIdx.x;
    if (i < NN * HD) {
        int node = i >> 8;
        int c    = i & 255;
        h[i] = emb[gt[node] * HD + c];
    }
    if (i < NN) deg[i] = 0.0f;
}

__global__ void deg_kernel(const int* __restrict__ dst, float* __restrict__ deg) {
    int e = blockIdx.x * blockDim.x + threadIdx.x;
    if (e < NE) atomicAdd(&deg[dst[e]], 1.0f);
}

__global__ void invdeg_kernel(const float* __restrict__ deg, float* __restrict__ inv) {
    int i = blockIdx.x * blockDim.x + threadIdx.x;
    if (i < NN) inv[i] = 1.0f / fmaxf(deg[i], 1.0f);
}

__global__ void zero_kernel(float4* __restrict__ p, int n4) {
    int i = blockIdx.x * blockDim.x + threadIdx.x;
    int stride = gridDim.x * blockDim.x;
    float4 z = make_float4(0.f, 0.f, 0.f, 0.f);
    for (; i < n4; i += stride) p[i] = z;
}

// ---------------- edge scatter: hN[dst] += leaky_relu(P[src] + w@W1b^T) ----
__global__ void edge_kernel(const int* __restrict__ src,
                            const int* __restrict__ dst,
                            const float* __restrict__ w,
                            const float* __restrict__ P,
                            const float* __restrict__ W1b,  // points at W1[l][0][256]
                            float* __restrict__ hN) {
    __shared__ float sW[3 * HD];   // sW[t*256 + c] = W1[l][c][256+t]
    for (int i = threadIdx.x; i < HD; i += blockDim.x) {
        sW[i]          = W1b[(size_t)i * W1_LD + 0];
        sW[HD + i]     = W1b[(size_t)i * W1_LD + 1];
        sW[2 * HD + i] = W1b[(size_t)i * W1_LD + 2];
    }
    __syncthreads();

    int warpId = (blockIdx.x * blockDim.x + threadIdx.x) >> 5;
    int lane   = threadIdx.x & 31;
    if (warpId >= NE) return;

    int s = src[warpId];
    int d = dst[warpId];
    float w0 = w[warpId * 3 + 0];
    float w1 = w[warpId * 3 + 1];
    float w2 = w[warpId * 3 + 2];

    const float* Ps  = P  + (size_t)s * HD;
    float*       out = hN + (size_t)d * HD;
#pragma unroll
    for (int j = 0; j < 2; j++) {
        int c = j * 128 + lane * 4;
        float4 p = *(const float4*)(Ps + c);
        float4 v;
        v.x = p.x + w0 * sW[c+0] + w1 * sW[HD + c+0] + w2 * sW[2*HD + c+0];
        v.y = p.y + w0 * sW[c+1] + w1 * sW[HD + c+1] + w2 * sW[2*HD + c+1];
        v.z = p.z + w0 * sW[c+2] + w1 * sW[HD + c+2] + w2 * sW[2*HD + c+2];
        v.w = p.w + w0 * sW[c+3] + w1 * sW[HD + c+3] + w2 * sW[2*HD + c+3];
        v.x = v.x > 0.0f ? v.x : 0.01f * v.x;
        v.y = v.y > 0.0f ? v.y : 0.01f * v.y;
        v.z = v.z > 0.0f ? v.z : 0.01f * v.z;
        v.w = v.w > 0.0f ? v.w : 0.01f * v.w;
        asm volatile("red.global.add.v4.f32 [%0], {%1, %2, %3, %4};"
                     :: "l"(out + c), "f"(v.x), "f"(v.y), "f"(v.z), "f"(v.w)
                     : "memory");
    }
}

// ---------------- tensor-core bf16 GEMM (mma.sync m16n8k16, 3-term split) --
// C tile 128x64 = act( A1 @ B[:, :K1]^T + (A2*rowscale) @ B[:, K1:]^T + bias )
// Smem: packed words [row][k2][hi|lo]; row stride RSW=24 words (16 used + 8 pad).
// Fragment pair (hi,lo) = one LDS.64; conflict-free per 16-lane phase: (12r+tg)%16.
#define BM 128
#define BN 64
#define KC 16
#define RSW 24   // 32-bit words per row

__global__ __launch_bounds__(256)
void mma_gemm_kernel(const float* __restrict__ A1, int K1,
                     const float* __restrict__ A2, int K2,
                     const float* __restrict__ rowscale,
                     const float* __restrict__ B, int ldb,
                     const float* __restrict__ bias,
                     float* __restrict__ C, int M, int N, int act) {
    __shared__ uint32_t Aw[BM * RSW];   // 12 KB
    __shared__ uint32_t Bw[BN * RSW];   //  6 KB

    int tid  = threadIdx.x;
    int wid  = tid >> 5;
    int lane = tid & 31;
    int grp  = lane >> 2;   // 0..7
    int tg   = lane & 3;    // 0..3
    int warp_m = wid & 3;   // 4 warps along M
    int warp_n = wid >> 2;  // 2 warps along N
    int m0 = warp_m * 32;
    int n0 = warp_n * 32;
    int mBase = blockIdx.y * BM;
    int nBase = blockIdx.x * BN;

    float acc[2][4][4];
#pragma unroll
    for (int i = 0; i < 2; i++)
#pragma unroll
        for (int j = 0; j < 4; j++)
#pragma unroll
            for (int q = 0; q < 4; q++) acc[i][j][q] = 0.0f;

    int K = K1 + K2;
    int nch = K / KC;
    int k1ch = K1 / KC;

    for (int kc = 0; kc < nch; kc++) {
        int kBase = kc * KC;
        bool useA2 = (kc >= k1ch);
        const float* Asrc = useA2 ? A2 : A1;
        int Ak  = useA2 ? (kBase - K1) : kBase;
        int Kld = useA2 ? K2 : K1;

        // A chunk: 128 rows x 16 k = 512 float4 jobs, 2 per thread
#pragma unroll
        for (int i = 0; i < 2; i++) {
            int job = tid + i * 256;
            int r  = job >> 2;          // 0..127
            int c4 = (job & 3) * 4;     // 0,4,8,12
            int row = mBase + r;
            if (row >= M) row = M - 1;
            float4 v = *(const float4*)(Asrc + (size_t)row * Kld + Ak + c4);
            if (useA2) {
                float sc = rowscale[row];
                v.x *= sc; v.y *= sc; v.z *= sc; v.w *= sc;
            }
            uint32_t w0, w1, w2, w3;
            split2(v.x, v.y, w0, w1);
            split2(v.z, v.w, w2, w3);
            *(uint4*)&Aw[r * RSW + c4] = make_uint4(w0, w1, w2, w3);
        }
        // B chunk: 64 rows x 8 k2-pairs = 512 jobs, 2 per thread (ldb may be odd)
#pragma unroll
        for (int i = 0; i < 2; i++) {
            int job = tid + i * 256;
            int nrow = job >> 3;        // 0..63
            int k2 = job & 7;           // 0..7
            const float* brow = B + (size_t)(nBase + nrow) * ldb + kBase + 2 * k2;
            uint32_t wh, wl;
            split2(brow[0], brow[1], wh, wl);
            *(uint2*)&Bw[nrow * RSW + 2 * k2] = make_uint2(wh, wl);
        }
        __syncthreads();

        // fragments: (hi,lo) word pairs, one LDS.64 each
        uint2 aF[2][4];
#pragma unroll
        for (int mt = 0; mt < 2; mt++) {
            int r = m0 + mt * 16 + grp;
            aF[mt][0] = *(uint2*)&Aw[r * RSW + 2 * tg];
            aF[mt][1] = *(uint2*)&Aw[(r + 8) * RSW + 2 * tg];
            aF[mt][2] = *(uint2*)&Aw[r * RSW + 2 * tg + 8];
            aF[mt][3] = *(uint2*)&Aw[(r + 8) * RSW + 2 * tg + 8];
        }
        uint2 bF[4][2];
#pragma unroll
        for (int nt = 0; nt < 4; nt++) {
            int nr = n0 + nt * 8 + grp;
            bF[nt][0] = *(uint2*)&Bw[nr * RSW + 2 * tg];
            bF[nt][1] = *(uint2*)&Bw[nr * RSW + 2 * tg + 8];
        }
#pragma unroll
        for (int mt = 0; mt < 2; mt++)
#pragma unroll
            for (int nt = 0; nt < 4; nt++) {
                float* c = acc[mt][nt];
                // hi*hi + lo*hi + hi*lo
                mma_bf16(c, aF[mt][0].x, aF[mt][1].x, aF[mt][2].x, aF[mt][3].x,
                         bF[nt][0].x, bF[nt][1].x);
                mma_bf16(c, aF[mt][0].y, aF[mt][1].y, aF[mt][2].y, aF[mt][3].y,
                         bF[nt][0].x, bF[nt][1].x);
                mma_bf16(c, aF[mt][0].x, aF[mt][1].x, aF[mt][2].x, aF[mt][3].x,
                         bF[nt][0].y, bF[nt][1].y);
            }
        __syncthreads();
    }

    // Epilogue (same fragment map as m16n8k8)
#pragma unroll
    for (int mt = 0; mt < 2; mt++) {
#pragma unroll
        for (int half = 0; half < 2; half++) {
            int row = mBase + m0 + mt * 16 + grp + half * 8;
            if (row >= M) continue;
#pragma unroll
            for (int nt = 0; nt < 4; nt++) {
                int col = nBase + n0 + nt * 8 + 2 * tg;
                float2 v;
                v.x = acc[mt][nt][half * 2 + 0];
                v.y = acc[mt][nt][half * 2 + 1];
                if (bias) { v.x += bias[col]; v.y += bias[col + 1]; }
                if (act)  { v.x = fmaxf(v.x, 0.0f); v.y = fmaxf(v.y, 0.0f); }
                *(float2*)(C + (size_t)row * N + col) = v;
            }
        }
    }
}

// ---------------- head dot: out[n] = x[n] . Wh2 + bh2 ----------------------
__global__ void head_dot_kernel(const float* __restrict__ x,
                                const float* __restrict__ Wh2,
                                const float* __restrict__ bh2,
                                float* __restrict__ out) {
    int node = blockIdx.x * (blockDim.x >> 5) + (threadIdx.x >> 5);
    int lane = threadIdx.x & 31;
    if (node >= NN) return;
    const float* xr = x + (size_t)node * HD;
    float s = 0.0f;
#pragma unroll
    for (int j = 0; j < 8; j++) {
        int c = lane + j * 32;
        s = fmaf(xr[c], Wh2[c], s);
    }
#pragma unroll
    for (int off = 16; off; off >>= 1)
        s += __shfl_xor_sync(0xffffffffu, s, off);
    if (lane == 0) out[node] = s + bh2[0];
}

// ---------------- launch ---------------------------------------------------
extern "C" void kernel_launch(void* const* d_in, const int* in_sizes, int n_in,
                              void* d_out, int out_size) {
    const int*   gate_type = (const int*)  d_in[0];
    const int*   src       = (const int*)  d_in[1];
    const int*   dst       = (const int*)  d_in[2];
    const float* w         = (const float*)d_in[3];
    const float* emb       = (const float*)d_in[4];
    const float* W1        = (const float*)d_in[5];
    const float* W2        = (const float*)d_in[6];
    const float* b2        = (const float*)d_in[7];
    const float* Wh1       = (const float*)d_in[8];
    const float* bh1       = (const float*)d_in[9];
    const float* Wh2       = (const float*)d_in[10];
    const float* bh2       = (const float*)d_in[11];
    float* out = (float*)d_out;

    float *hA, *hB, *P, *hN, *deg, *invdeg;
    cudaGetSymbolAddress((void**)&hA,     g_hA);
    cudaGetSymbolAddress((void**)&hB,     g_hB);
    cudaGetSymbolAddress((void**)&P,      g_P);
    cudaGetSymbolAddress((void**)&hN,     g_hN);
    cudaGetSymbolAddress((void**)&deg,    g_deg);
    cudaGetSymbolAddress((void**)&invdeg, g_invdeg);

    // h0 = emb[gate_type]; deg = in-degree; invdeg = 1/max(deg,1)
    init_kernel<<<(NN * HD + 255) / 256, 256>>>(gate_type, emb, hA, deg);
    deg_kernel<<<(NE + 255) / 256, 256>>>(dst, deg);
    invdeg_kernel<<<(NN + 255) / 256, 256>>>(deg, invdeg);

    dim3 ggrid(HD / BN, (NN + BM - 1) / BM);   // (4, 782)
    float* hcur = hA;
    float* hnext = hB;

    for (int l = 0; l < NL; l++) {
        const float* W1l = W1 + (size_t)l * HD * W1_LD;
        const float* W2l = W2 + (size_t)l * HD * W2_LD;
        const float* b2l = b2 + (size_t)l * HD;

        // P = h @ W1[:, :256]^T   (node-space; avoids the 8x larger edge GEMM)
        mma_gemm_kernel<<<ggrid, 256>>>(hcur, HD, nullptr, 0, nullptr,
                                        W1l, W1_LD, nullptr, P, NN, HD, 0);

        zero_kernel<<<2048, 256>>>((float4*)hN, NN * HD / 4);

        // hN[dst] += leaky_relu(P[src] + w @ W1[:, 256:259]^T)
        edge_kernel<<<(NE * 32 + 255) / 256, 256>>>(src, dst, w, P, W1l + HD, hN);

        // h' = relu(h @ W2[:, :256]^T + (hN*invdeg) @ W2[:, 256:]^T + b2)
        mma_gemm_kernel<<<ggrid, 256>>>(hcur, HD, hN, HD, invdeg,
                                        W2l, W2_LD, b2l, hnext, NN, HD, 1);

        float* t = hcur; hcur = hnext; hnext = t;
    }

    // head: x = relu(h @ Wh1^T + bh1); out = x @ Wh2^T + bh2
    mma_gemm_kernel<<<ggrid, 256>>>(hcur, HD, nullptr, 0, nullptr,
                                    Wh1, HD, bh1, P, NN, HD, 1);
    head_dot_kernel<<<(NN * 32 + 255) / 256, 256>>>(P, Wh2, bh2, out);
}

// round 9
// speedup vs baseline: 1.6796x; 1.2479x over previous
#include <cuda_runtime.h>
#include <cuda_bf16.h>
#include <cstdint>
#include <cstddef>

// Problem constants
#define NN 100000      // nodes
#define NE 800000      // edges
#define HD 256         // hidden dim
#define NL 6           // layers
#define W1_LD 259      // H + 3 edge features
#define W2_LD 512      // H + INTER

// ---------------- scratch (device globals; no runtime allocation) ----------
__device__ float g_hA[(size_t)NN * HD];
__device__ float g_hB[(size_t)NN * HD];
__device__ float g_P [(size_t)NN * HD];
__device__ float g_hN[(size_t)NN * HD];
__device__ float g_deg[NN];
__device__ float g_invdeg[NN];

// split a,b into bf16 (hi, lo) packed words
__device__ __forceinline__ void split2(float a, float b, uint32_t& hi, uint32_t& lo) {
    __nv_bfloat16 ha = __float2bfloat16(a);
    __nv_bfloat16 hb = __float2bfloat16(b);
    __nv_bfloat16 la = __float2bfloat16(a - __bfloat162float(ha));
    __nv_bfloat16 lb = __float2bfloat16(b - __bfloat162float(hb));
    __nv_bfloat162 h2 = __halves2bfloat162(ha, hb);
    __nv_bfloat162 l2 = __halves2bfloat162(la, lb);
    hi = *reinterpret_cast<uint32_t*>(&h2);
    lo = *reinterpret_cast<uint32_t*>(&l2);
}

__device__ __forceinline__ void mma_bf16(float* c,
                                         uint32_t a0, uint32_t a1, uint32_t a2, uint32_t a3,
                                         uint32_t b0, uint32_t b1) {
    asm volatile(
        "mma.sync.aligned.m16n8k16.row.col.f32.bf16.bf16.f32 "
        "{%0,%1,%2,%3}, {%4,%5,%6,%7}, {%8,%9}, {%0,%1,%2,%3};"
        : "+f"(c[0]), "+f"(c[1]), "+f"(c[2]), "+f"(c[3])
        : "r"(a0), "r"(a1), "r"(a2), "r"(a3), "r"(b0), "r"(b1));
}

// ---------------- small elementwise kernels --------------------------------
__global__ void init_kernel(const int* __restrict__ gt,
                            const float* __restrict__ emb,
                            float* __restrict__ h,
                            float* __restrict__ deg) {
    int i = blockIdx.x * blockDim.x + threadIdx.x;
    if (i < NN * HD) {
        int node = i >> 8;
        int c    = i & 255;
        h[i] = emb[gt[node] * HD + c];
    }
    if (i < NN) deg[i] = 0.0f;
}

__global__ void deg_kernel(const int* __restrict__ dst, float* __restrict__ deg) {
    int e = blockIdx.x * blockDim.x + threadIdx.x;
    if (e < NE) atomicAdd(&deg[dst[e]], 1.0f);
}

__global__ void invdeg_kernel(const float* __restrict__ deg, float* __restrict__ inv) {
    int i = blockIdx.x * blockDim.x + threadIdx.x;
    if (i < NN) inv[i] = 1.0f / fmaxf(deg[i], 1.0f);
}

__global__ void zero_kernel(float4* __restrict__ p, int n4) {
    int i = blockIdx.x * blockDim.x + threadIdx.x;
    int stride = gridDim.x * blockDim.x;
    float4 z = make_float4(0.f, 0.f, 0.f, 0.f);
    for (; i < n4; i += stride) p[i] = z;
}

// ---------------- edge scatter: hN[dst] += leaky_relu(P[src] + w@W1b^T) ----
__global__ void edge_kernel(const int* __restrict__ src,
                            const int* __restrict__ dst,
                            const float* __restrict__ w,
                            const float* __restrict__ P,
                            const float* __restrict__ W1b,  // points at W1[l][0][256]
                            float* __restrict__ hN) {
    __shared__ float sW[3 * HD];   // sW[t*256 + c] = W1[l][c][256+t]
    for (int i = threadIdx.x; i < HD; i += blockDim.x) {
        sW[i]          = W1b[(size_t)i * W1_LD + 0];
        sW[HD + i]     = W1b[(size_t)i * W1_LD + 1];
        sW[2 * HD + i] = W1b[(size_t)i * W1_LD + 2];
    }
    __syncthreads();

    int warpId = (blockIdx.x * blockDim.x + threadIdx.x) >> 5;
    int lane   = threadIdx.x & 31;
    if (warpId >= NE) return;

    int s = src[warpId];
    int d = dst[warpId];
    float w0 = w[warpId * 3 + 0];
    float w1 = w[warpId * 3 + 1];
    float w2 = w[warpId * 3 + 2];

    const float* Ps  = P  + (size_t)s * HD;
    float*       out = hN + (size_t)d * HD;
#pragma unroll
    for (int j = 0; j < 2; j++) {
        int c = j * 128 + lane * 4;
        float4 p = *(const float4*)(Ps + c);
        float4 v;
        v.x = p.x + w0 * sW[c+0] + w1 * sW[HD + c+0] + w2 * sW[2*HD + c+0];
        v.y = p.y + w0 * sW[c+1] + w1 * sW[HD + c+1] + w2 * sW[2*HD + c+1];
        v.z = p.z + w0 * sW[c+2] + w1 * sW[HD + c+2] + w2 * sW[2*HD + c+2];
        v.w = p.w + w0 * sW[c+3] + w1 * sW[HD + c+3] + w2 * sW[2*HD + c+3];
        v.x = v.x > 0.0f ? v.x : 0.01f * v.x;
        v.y = v.y > 0.0f ? v.y : 0.01f * v.y;
        v.z = v.z > 0.0f ? v.z : 0.01f * v.z;
        v.w = v.w > 0.0f ? v.w : 0.01f * v.w;
        asm volatile("red.global.add.v4.f32 [%0], {%1, %2, %3, %4};"
                     :: "l"(out + c), "f"(v.x), "f"(v.y), "f"(v.z), "f"(v.w)
                     : "memory");
    }
}

// ---------------- tensor-core bf16 GEMM (mma.sync m16n8k16, 3-term split) --
// C tile 128x64 = act( A1 @ B[:, :K1]^T + (A2*rowscale) @ B[:, K1:]^T + bias )
// Smem: packed words [row][k2][hi|lo]; row stride RSW=40 words (32 used + 8 pad).
// KC=32: 2 syncs per 32-wide K chunk (half the barriers of KC=16).
#define BM 128
#define BN 64
#define KC 32
#define RSW 40   // 32-bit words per row

__global__ __launch_bounds__(256, 3)
void mma_gemm_kernel(const float* __restrict__ A1, int K1,
                     const float* __restrict__ A2, int K2,
                     const float* __restrict__ rowscale,
                     const float* __restrict__ B, int ldb,
                     const float* __restrict__ bias,
                     float* __restrict__ C, int M, int N, int act) {
    __shared__ uint32_t Aw[BM * RSW];   // 20 KB
    __shared__ uint32_t Bw[BN * RSW];   // 10 KB

    int tid  = threadIdx.x;
    int wid  = tid >> 5;
    int lane = tid & 31;
    int grp  = lane >> 2;   // 0..7
    int tg   = lane & 3;    // 0..3
    int warp_m = wid & 3;   // 4 warps along M
    int warp_n = wid >> 2;  // 2 warps along N
    int m0 = warp_m * 32;
    int n0 = warp_n * 32;
    int mBase = blockIdx.y * BM;
    int nBase = blockIdx.x * BN;

    float acc[2][4][4];
#pragma unroll
    for (int i = 0; i < 2; i++)
#pragma unroll
        for (int j = 0; j < 4; j++)
#pragma unroll
            for (int q = 0; q < 4; q++) acc[i][j][q] = 0.0f;

    int K = K1 + K2;
    int nch = K / KC;
    int k1ch = K1 / KC;

    for (int kc = 0; kc < nch; kc++) {
        int kBase = kc * KC;
        bool useA2 = (kc >= k1ch);
        const float* Asrc = useA2 ? A2 : A1;
        int Ak  = useA2 ? (kBase - K1) : kBase;
        int Kld = useA2 ? K2 : K1;

        // A chunk: 128 rows x 32 k = 1024 float4 jobs, 4 per thread
#pragma unroll
        for (int i = 0; i < 4; i++) {
            int job = tid + i * 256;
            int r  = job >> 3;          // 0..127
            int c4 = (job & 7) * 4;     // 0,4,...,28
            int row = mBase + r;
            if (row >= M) row = M - 1;
            float4 v = *(const float4*)(Asrc + (size_t)row * Kld + Ak + c4);
            if (useA2) {
                float sc = rowscale[row];
                v.x *= sc; v.y *= sc; v.z *= sc; v.w *= sc;
            }
            uint32_t w0, w1, w2, w3;
            split2(v.x, v.y, w0, w1);
            split2(v.z, v.w, w2, w3);
            *(uint4*)&Aw[r * RSW + c4] = make_uint4(w0, w1, w2, w3);
        }
        // B chunk: 64 rows x 16 k2-pairs = 1024 jobs, 4 per thread (ldb may be odd)
#pragma unroll
        for (int i = 0; i < 4; i++) {
            int job = tid + i * 256;
            int nrow = job >> 4;        // 0..63
            int k2 = job & 15;          // 0..15
            const float* brow = B + (size_t)(nBase + nrow) * ldb + kBase + 2 * k2;
            uint32_t wh, wl;
            split2(brow[0], brow[1], wh, wl);
            *(uint2*)&Bw[nrow * RSW + 2 * k2] = make_uint2(wh, wl);
        }
        __syncthreads();

#pragma unroll
        for (int ks = 0; ks < 2; ks++) {   // two 16-wide sub-chunks
            int kw = ks * 16;              // word offset of sub-chunk
            uint2 aF[2][4];
#pragma unroll
            for (int mt = 0; mt < 2; mt++) {
                int r = m0 + mt * 16 + grp;
                aF[mt][0] = *(uint2*)&Aw[r * RSW + kw + 2 * tg];
                aF[mt][1] = *(uint2*)&Aw[(r + 8) * RSW + kw + 2 * tg];
                aF[mt][2] = *(uint2*)&Aw[r * RSW + kw + 2 * tg + 8];
                aF[mt][3] = *(uint2*)&Aw[(r + 8) * RSW + kw + 2 * tg + 8];
            }
            uint2 bF[4][2];
#pragma unroll
            for (int nt = 0; nt < 4; nt++) {
                int nr = n0 + nt * 8 + grp;
                bF[nt][0] = *(uint2*)&Bw[nr * RSW + kw + 2 * tg];
                bF[nt][1] = *(uint2*)&Bw[nr * RSW + kw + 2 * tg + 8];
            }
#pragma unroll
            for (int mt = 0; mt < 2; mt++)
#pragma unroll
                for (int nt = 0; nt < 4; nt++) {
                    float* c = acc[mt][nt];
                    // hi*hi + lo*hi + hi*lo
                    mma_bf16(c, aF[mt][0].x, aF[mt][1].x, aF[mt][2].x, aF[mt][3].x,
                             bF[nt][0].x, bF[nt][1].x);
                    mma_bf16(c, aF[mt][0].y, aF[mt][1].y, aF[mt][2].y, aF[mt][3].y,
                             bF[nt][0].x, bF[nt][1].x);
                    mma_bf16(c, aF[mt][0].x, aF[mt][1].x, aF[mt][2].x, aF[mt][3].x,
                             bF[nt][0].y, bF[nt][1].y);
                }
        }
        __syncthreads();
    }

    // Epilogue (same fragment map as m16n8k8)
#pragma unroll
    for (int mt = 0; mt < 2; mt++) {
#pragma unroll
        for (int half = 0; half < 2; half++) {
            int row = mBase + m0 + mt * 16 + grp + half * 8;
            if (row >= M) continue;
#pragma unroll
            for (int nt = 0; nt < 4; nt++) {
                int col = nBase + n0 + nt * 8 + 2 * tg;
                float2 v;
                v.x = acc[mt][nt][half * 2 + 0];
                v.y = acc[mt][nt][half * 2 + 1];
                if (bias) { v.x += bias[col]; v.y += bias[col + 1]; }
                if (act)  { v.x = fmaxf(v.x, 0.0f); v.y = fmaxf(v.y, 0.0f); }
                *(float2*)(C + (size_t)row * N + col) = v;
            }
        }
    }
}

// ---------------- head dot: out[n] = x[n] . Wh2 + bh2 ----------------------
__global__ void head_dot_kernel(const float* __restrict__ x,
                                const float* __restrict__ Wh2,
                                const float* __restrict__ bh2,
                                float* __restrict__ out) {
    int node = blockIdx.x * (blockDim.x >> 5) + (threadIdx.x >> 5);
    int lane = threadIdx.x & 31;
    if (node >= NN) return;
    const float* xr = x + (size_t)node * HD;
    float s = 0.0f;
#pragma unroll
    for (int j = 0; j < 8; j++) {
        int c = lane + j * 32;
        s = fmaf(xr[c], Wh2[c], s);
    }
#pragma unroll
    for (int off = 16; off; off >>= 1)
        s += __shfl_xor_sync(0xffffffffu, s, off);
    if (lane == 0) out[node] = s + bh2[0];
}

// ---------------- launch ---------------------------------------------------
extern "C" void kernel_launch(void* const* d_in, const int* in_sizes, int n_in,
                              void* d_out, int out_size) {
    const int*   gate_type = (const int*)  d_in[0];
    const int*   src       = (const int*)  d_in[1];
    const int*   dst       = (const int*)  d_in[2];
    const float* w         = (const float*)d_in[3];
    const float* emb       = (const float*)d_in[4];
    const float* W1        = (const float*)d_in[5];
    const float* W2        = (const float*)d_in[6];
    const float* b2        = (const float*)d_in[7];
    const float* Wh1       = (const float*)d_in[8];
    const float* bh1       = (const float*)d_in[9];
    const float* Wh2       = (const float*)d_in[10];
    const float* bh2       = (const float*)d_in[11];
    float* out = (float*)d_out;

    float *hA, *hB, *P, *hN, *deg, *invdeg;
    cudaGetSymbolAddress((void**)&hA,     g_hA);
    cudaGetSymbolAddress((void**)&hB,     g_hB);
    cudaGetSymbolAddress((void**)&P,      g_P);
    cudaGetSymbolAddress((void**)&hN,     g_hN);
    cudaGetSymbolAddress((void**)&deg,    g_deg);
    cudaGetSymbolAddress((void**)&invdeg, g_invdeg);

    // h0 = emb[gate_type]; deg = in-degree; invdeg = 1/max(deg,1)
    init_kernel<<<(NN * HD + 255) / 256, 256>>>(gate_type, emb, hA, deg);
    deg_kernel<<<(NE + 255) / 256, 256>>>(dst, deg);
    invdeg_kernel<<<(NN + 255) / 256, 256>>>(deg, invdeg);

    dim3 ggrid(HD / BN, (NN + BM - 1) / BM);   // (4, 782)
    float* hcur = hA;
    float* hnext = hB;

    for (int l = 0; l < NL; l++) {
        const float* W1l = W1 + (size_t)l * HD * W1_LD;
        const float* W2l = W2 + (size_t)l * HD * W2_LD;
        const float* b2l = b2 + (size_t)l * HD;

        // P = h @ W1[:, :256]^T   (node-space; avoids the 8x larger edge GEMM)
        mma_gemm_kernel<<<ggrid, 256>>>(hcur, HD, nullptr, 0, nullptr,
                                        W1l, W1_LD, nullptr, P, NN, HD, 0);

        zero_kernel<<<2048, 256>>>((float4*)hN, NN * HD / 4);

        // hN[dst] += leaky_relu(P[src] + w @ W1[:, 256:259]^T)
        edge_kernel<<<(NE * 32 + 255) / 256, 256>>>(src, dst, w, P, W1l + HD, hN);

        // h' = relu(h @ W2[:, :256]^T + (hN*invdeg) @ W2[:, 256:]^T + b2)
        mma_gemm_kernel<<<ggrid, 256>>>(hcur, HD, hN, HD, invdeg,
                                        W2l, W2_LD, b2l, hnext, NN, HD, 1);

        float* t = hcur; hcur = hnext; hnext = t;
    }

    // head: x = relu(h @ Wh1^T + bh1); out = x @ Wh2^T + bh2
    mma_gemm_kernel<<<ggrid, 256>>>(hcur, HD, nullptr, 0, nullptr,
                                    Wh1, HD, bh1, P, NN, HD, 1);
    head_dot_kernel<<<(NN * 32 + 255) / 256, 256>>>(P, Wh2, bh2, out);
}

// round 10
// speedup vs baseline: 1.9073x; 1.1356x over previous
#include <cuda_runtime.h>
#include <cuda_bf16.h>
#include <cstdint>
#include <cstddef>

// Problem constants
#define NN 100000      // nodes
#define NE 800000      // edges
#define HD 256         // hidden dim
#define NL 6           // layers
#define W1_LD 259      // H + 3 edge features
#define W2_LD 512      // H + INTER
#define HP 128         // packed pairs per node row (HD/2)

// ---------------- scratch (device globals; no runtime allocation) ----------
__device__ float g_P [(size_t)NN * HD];
__device__ float g_hN[(size_t)NN * HD];
__device__ float g_deg[NN];
__device__ float g_invdeg[NN];
__device__ uint2 g_hPkA[(size_t)NN * HP];
__device__ uint2 g_hPkB[(size_t)NN * HP];
__device__ uint2 g_hNp [(size_t)NN * HP];
__device__ uint2 g_W1p [NL * 256 * 128];
__device__ uint2 g_W2p [NL * 256 * 256];
__device__ uint2 g_Wh1p[256 * 128];

// split a,b into bf16 (hi, lo) packed words
__device__ __forceinline__ void split2(float a, float b, uint32_t& hi, uint32_t& lo) {
    __nv_bfloat16 ha = __float2bfloat16(a);
    __nv_bfloat16 hb = __float2bfloat16(b);
    __nv_bfloat16 la = __float2bfloat16(a - __bfloat162float(ha));
    __nv_bfloat16 lb = __float2bfloat16(b - __bfloat162float(hb));
    __nv_bfloat162 h2 = __halves2bfloat162(ha, hb);
    __nv_bfloat162 l2 = __halves2bfloat162(la, lb);
    hi = *reinterpret_cast<uint32_t*>(&h2);
    lo = *reinterpret_cast<uint32_t*>(&l2);
}

__device__ __forceinline__ void mma_bf16(float* c,
                                         uint32_t a0, uint32_t a1, uint32_t a2, uint32_t a3,
                                         uint32_t b0, uint32_t b1) {
    asm volatile(
        "mma.sync.aligned.m16n8k16.row.col.f32.bf16.bf16.f32 "
        "{%0,%1,%2,%3}, {%4,%5,%6,%7}, {%8,%9}, {%0,%1,%2,%3};"
        : "+f"(c[0]), "+f"(c[1]), "+f"(c[2]), "+f"(c[3])
        : "r"(a0), "r"(a1), "r"(a2), "r"(a3), "r"(b0), "r"(b1));
}

__device__ __forceinline__ void cp_async16(uint32_t smem_dst, const void* gsrc) {
    asm volatile("cp.async.cg.shared.global [%0], [%1], 16;"
                 :: "r"(smem_dst), "l"(gsrc) : "memory");
}
#define CP_COMMIT() asm volatile("cp.async.commit_group;" ::: "memory")
#define CP_WAIT0()  asm volatile("cp.async.wait_group 0;" ::: "memory")

// ---------------- small elementwise kernels --------------------------------
__global__ void init_kernel(const int* __restrict__ gt,
                            const float* __restrict__ emb,
                            uint2* __restrict__ hp,
                            float* __restrict__ deg) {
    int i = blockIdx.x * blockDim.x + threadIdx.x;
    if (i < NN * HP) {
        int node = i >> 7;
        int j    = i & 127;
        const float* e = emb + gt[node] * HD + 2 * j;
        uint32_t hi, lo;
        split2(e[0], e[1], hi, lo);
        hp[i] = make_uint2(hi, lo);
    }
    if (i < NN) deg[i] = 0.0f;
}

__global__ void deg_kernel(const int* __restrict__ dst, float* __restrict__ deg) {
    int e = blockIdx.x * blockDim.x + threadIdx.x;
    if (e < NE) atomicAdd(&deg[dst[e]], 1.0f);
}

__global__ void invdeg_kernel(const float* __restrict__ deg, float* __restrict__ inv) {
    int i = blockIdx.x * blockDim.x + threadIdx.x;
    if (i < NN) inv[i] = 1.0f / fmaxf(deg[i], 1.0f);
}

__global__ void zero_kernel(float4* __restrict__ p, int n4) {
    int i = blockIdx.x * blockDim.x + threadIdx.x;
    int stride = gridDim.x * blockDim.x;
    float4 z = make_float4(0.f, 0.f, 0.f, 0.f);
    for (; i < n4; i += stride) p[i] = z;
}

// pack fp32 [rows, srcld] -> uint2 hi/lo [rows, kp], optional per-row scale
__global__ void pack_kernel(const float* __restrict__ src, int srcld, int kp,
                            int total, const float* __restrict__ rowscale,
                            uint2* __restrict__ dst) {
    int i = blockIdx.x * blockDim.x + threadIdx.x;
    if (i >= total) return;
    int r = i / kp, j = i - r * kp;
    float a = src[(size_t)r * srcld + 2 * j];
    float b = src[(size_t)r * srcld + 2 * j + 1];
    if (rowscale) { float s = rowscale[r]; a *= s; b *= s; }
    uint32_t hi, lo;
    split2(a, b, hi, lo);
    dst[(size_t)r * kp + j] = make_uint2(hi, lo);
}

// ---------------- edge scatter: hN[dst] += leaky_relu(P[src] + w@W1b^T) ----
__global__ void edge_kernel(const int* __restrict__ src,
                            const int* __restrict__ dst,
                            const float* __restrict__ w,
                            const float* __restrict__ P,
                            const float* __restrict__ W1b,  // points at W1[l][0][256]
                            float* __restrict__ hN) {
    __shared__ float sW[3 * HD];
    for (int i = threadIdx.x; i < HD; i += blockDim.x) {
        sW[i]          = W1b[(size_t)i * W1_LD + 0];
        sW[HD + i]     = W1b[(size_t)i * W1_LD + 1];
        sW[2 * HD + i] = W1b[(size_t)i * W1_LD + 2];
    }
    __syncthreads();

    int warpId = (blockIdx.x * blockDim.x + threadIdx.x) >> 5;
    int lane   = threadIdx.x & 31;
    if (warpId >= NE) return;

    int s = src[warpId];
    int d = dst[warpId];
    float w0 = w[warpId * 3 + 0];
    float w1 = w[warpId * 3 + 1];
    float w2 = w[warpId * 3 + 2];

    const float* Ps  = P  + (size_t)s * HD;
    float*       out = hN + (size_t)d * HD;
#pragma unroll
    for (int j = 0; j < 2; j++) {
        int c = j * 128 + lane * 4;
        float4 p = *(const float4*)(Ps + c);
        float4 v;
        v.x = p.x + w0 * sW[c+0] + w1 * sW[HD + c+0] + w2 * sW[2*HD + c+0];
        v.y = p.y + w0 * sW[c+1] + w1 * sW[HD + c+1] + w2 * sW[2*HD + c+1];
        v.z = p.z + w0 * sW[c+2] + w1 * sW[HD + c+2] + w2 * sW[2*HD + c+2];
        v.w = p.w + w0 * sW[c+3] + w1 * sW[HD + c+3] + w2 * sW[2*HD + c+3];
        v.x = v.x > 0.0f ? v.x : 0.01f * v.x;
        v.y = v.y > 0.0f ? v.y : 0.01f * v.y;
        v.z = v.z > 0.0f ? v.z : 0.01f * v.z;
        v.w = v.w > 0.0f ? v.w : 0.01f * v.w;
        asm volatile("red.global.add.v4.f32 [%0], {%1, %2, %3, %4};"
                     :: "l"(out + c), "f"(v.x), "f"(v.y), "f"(v.z), "f"(v.w)
                     : "memory");
    }
}

// ---------------- tensor-core bf16 GEMM: packed operands + cp.async pipe ---
// C tile 128x64 = act( A1p @ B[:, :K1]^T + A2p @ B[:, K1:]^T + bias )
// Operands pre-split in global as uint2 (hi,lo) per 2 floats.
// Smem: 2-stage ring, KC=32, RW=32 words/row (no pad), XOR-quadrant swizzle
// pair' = pair ^ ((row&3)<<2). 48 KB static total.
#define BM 128
#define BN 64
#define KC 32
#define RW 32   // 32-bit words per row

__global__ __launch_bounds__(256, 3)
void mma_gemm_kernel(const uint2* __restrict__ A1, int K1,
                     const uint2* __restrict__ A2, int K2,
                     const uint2* __restrict__ Bp,
                     const float* __restrict__ bias,
                     float* __restrict__ C, uint2* __restrict__ Cp,
                     int M, int N, int act) {
    __shared__ uint32_t Aw[2][BM * RW];   // 2 x 16 KB
    __shared__ uint32_t Bw[2][BN * RW];   // 2 x  8 KB

    int tid  = threadIdx.x;
    int wid  = tid >> 5;
    int lane = tid & 31;
    int grp  = lane >> 2;   // 0..7
    int tg   = lane & 3;    // 0..3
    int warp_m = wid & 3;   // 4 warps along M
    int warp_n = wid >> 2;  // 2 warps along N
    int m0 = warp_m * 32;
    int n0 = warp_n * 32;
    int mBase = blockIdx.y * BM;
    int nBase = blockIdx.x * BN;

    int K = K1 + K2;
    int nch = K / KC;
    int k1ch = K1 / KC;
    int kpB = K >> 1;        // B row pairs

    uint32_t aSm[2], bSm[2];
    aSm[0] = (uint32_t)__cvta_generic_to_shared(&Aw[0][0]);
    aSm[1] = (uint32_t)__cvta_generic_to_shared(&Aw[1][0]);
    bSm[0] = (uint32_t)__cvta_generic_to_shared(&Bw[0][0]);
    bSm[1] = (uint32_t)__cvta_generic_to_shared(&Bw[1][0]);

    float acc[2][4][4];
#pragma unroll
    for (int i = 0; i < 2; i++)
#pragma unroll
        for (int j = 0; j < 4; j++)
#pragma unroll
            for (int q = 0; q < 4; q++) acc[i][j][q] = 0.0f;

    // -- async load of one K-chunk into stage b --
    auto load_chunk = [&](int kc, int b) {
        int kp = kc * (KC / 2);               // global pair offset
        bool u2 = (kc >= k1ch);
        const uint2* Ap = u2 ? A2 : A1;
        int kpa = u2 ? kp - (K1 >> 1) : kp;
        int lda = (u2 ? K2 : K1) >> 1;
        // A: 128 rows x 8 16B-segments = 1024 jobs, 4/thread
#pragma unroll
        for (int i = 0; i < 4; i++) {
            int job = tid + i * 256;
            int r = job >> 3, s = job & 7;
            int row = mBase + r; if (row >= M) row = M - 1;
            const uint2* g = Ap + (size_t)row * lda + kpa + 2 * s;
            uint32_t d = aSm[b] + (uint32_t)(r * RW + ((4 * s) ^ ((r & 3) << 3))) * 4u;
            cp_async16(d, g);
        }
        // B: 64 rows x 8 segments = 512 jobs, 2/thread
#pragma unroll
        for (int i = 0; i < 2; i++) {
            int job = tid + i * 256;
            int r = job >> 3, s = job & 7;
            const uint2* g = Bp + (size_t)(nBase + r) * kpB + kp + 2 * s;
            uint32_t d = bSm[b] + (uint32_t)(r * RW + ((4 * s) ^ ((r & 3) << 3))) * 4u;
            cp_async16(d, g);
        }
    };

    load_chunk(0, 0);
    CP_COMMIT();

    for (int kc = 0; kc < nch; kc++) {
        int b = kc & 1;
        CP_WAIT0();
        __syncthreads();
        if (kc + 1 < nch) { load_chunk(kc + 1, (kc + 1) & 1); CP_COMMIT(); }

        const uint32_t* A = Aw[b];
        const uint32_t* Bs = Bw[b];
#pragma unroll
        for (int ks = 0; ks < 2; ks++) {
            uint2 aF[2][4];
#pragma unroll
            for (int mt = 0; mt < 2; mt++) {
                int r = m0 + mt * 16 + grp;
                int sw = (r & 3) << 2;
                int p0 = (ks * 8 + tg) ^ sw;
                int p1 = (ks * 8 + tg + 4) ^ sw;
                aF[mt][0] = *(const uint2*)&A[r * RW + 2 * p0];
                aF[mt][1] = *(const uint2*)&A[(r + 8) * RW + 2 * p0];
                aF[mt][2] = *(const uint2*)&A[r * RW + 2 * p1];
                aF[mt][3] = *(const uint2*)&A[(r + 8) * RW + 2 * p1];
            }
            uint2 bF[4][2];
#pragma unroll
            for (int nt = 0; nt < 4; nt++) {
                int nr = n0 + nt * 8 + grp;
                int sw = (nr & 3) << 2;
                bF[nt][0] = *(const uint2*)&Bs[nr * RW + 2 * ((ks * 8 + tg) ^ sw)];
                bF[nt][1] = *(const uint2*)&Bs[nr * RW + 2 * ((ks * 8 + tg + 4) ^ sw)];
            }
#pragma unroll
            for (int mt = 0; mt < 2; mt++)
#pragma unroll
                for (int nt = 0; nt < 4; nt++) {
                    float* c = acc[mt][nt];
                    mma_bf16(c, aF[mt][0].x, aF[mt][1].x, aF[mt][2].x, aF[mt][3].x,
                             bF[nt][0].x, bF[nt][1].x);
                    mma_bf16(c, aF[mt][0].y, aF[mt][1].y, aF[mt][2].y, aF[mt][3].y,
                             bF[nt][0].x, bF[nt][1].x);
                    mma_bf16(c, aF[mt][0].x, aF[mt][1].x, aF[mt][2].x, aF[mt][3].x,
                             bF[nt][0].y, bF[nt][1].y);
                }
        }
        __syncthreads();
    }

    // Epilogue: fp32 C or packed Cp
#pragma unroll
    for (int mt = 0; mt < 2; mt++) {
#pragma unroll
        for (int half = 0; half < 2; half++) {
            int row = mBase + m0 + mt * 16 + grp + half * 8;
            if (row >= M) continue;
#pragma unroll
            for (int nt = 0; nt < 4; nt++) {
                int col = nBase + n0 + nt * 8 + 2 * tg;
                float2 v;
                v.x = acc[mt][nt][half * 2 + 0];
                v.y = acc[mt][nt][half * 2 + 1];
                if (bias) { v.x += bias[col]; v.y += bias[col + 1]; }
                if (act)  { v.x = fmaxf(v.x, 0.0f); v.y = fmaxf(v.y, 0.0f); }
                if (Cp) {
                    uint32_t hi, lo;
                    split2(v.x, v.y, hi, lo);
                    Cp[(size_t)row * (N >> 1) + (col >> 1)] = make_uint2(hi, lo);
                } else {
                    *(float2*)(C + (size_t)row * N + col) = v;
                }
            }
        }
    }
}

// ---------------- head dot: out[n] = x[n] . Wh2 + bh2 ----------------------
__global__ void head_dot_kernel(const float* __restrict__ x,
                                const float* __restrict__ Wh2,
                                const float* __restrict__ bh2,
                                float* __restrict__ out) {
    int node = blockIdx.x * (blockDim.x >> 5) + (threadIdx.x >> 5);
    int lane = threadIdx.x & 31;
    if (node >= NN) return;
    const float* xr = x + (size_t)node * HD;
    float s = 0.0f;
#pragma unroll
    for (int j = 0; j < 8; j++) {
        int c = lane + j * 32;
        s = fmaf(xr[c], Wh2[c], s);
    }
#pragma unroll
    for (int off = 16; off; off >>= 1)
        s += __shfl_xor_sync(0xffffffffu, s, off);
    if (lane == 0) out[node] = s + bh2[0];
}

// ---------------- launch ---------------------------------------------------
extern "C" void kernel_launch(void* const* d_in, const int* in_sizes, int n_in,
                              void* d_out, int out_size) {
    const int*   gate_type = (const int*)  d_in[0];
    const int*   src       = (const int*)  d_in[1];
    const int*   dst       = (const int*)  d_in[2];
    const float* w         = (const float*)d_in[3];
    const float* emb       = (const float*)d_in[4];
    const float* W1        = (const float*)d_in[5];
    const float* W2        = (const float*)d_in[6];
    const float* b2        = (const float*)d_in[7];
    const float* Wh1       = (const float*)d_in[8];
    const float* bh1       = (const float*)d_in[9];
    const float* Wh2       = (const float*)d_in[10];
    const float* bh2       = (const float*)d_in[11];
    float* out = (float*)d_out;

    float *P, *hN, *deg, *invdeg;
    uint2 *hPkA, *hPkB, *hNp, *W1p, *W2p, *Wh1p;
    cudaGetSymbolAddress((void**)&P,      g_P);
    cudaGetSymbolAddress((void**)&hN,     g_hN);
    cudaGetSymbolAddress((void**)&deg,    g_deg);
    cudaGetSymbolAddress((void**)&invdeg, g_invdeg);
    cudaGetSymbolAddress((void**)&hPkA,   g_hPkA);
    cudaGetSymbolAddress((void**)&hPkB,   g_hPkB);
    cudaGetSymbolAddress((void**)&hNp,    g_hNp);
    cudaGetSymbolAddress((void**)&W1p,    g_W1p);
    cudaGetSymbolAddress((void**)&W2p,    g_W2p);
    cudaGetSymbolAddress((void**)&Wh1p,   g_Wh1p);

    // h0 packed = split(emb[gate_type]); deg; invdeg
    init_kernel<<<(NN * HP + 255) / 256, 256>>>(gate_type, emb, hPkA, deg);
    deg_kernel<<<(NE + 255) / 256, 256>>>(dst, deg);
    invdeg_kernel<<<(NN + 255) / 256, 256>>>(deg, invdeg);

    // pack weights (once per launch)
    for (int l = 0; l < NL; l++) {
        pack_kernel<<<(256 * 128 + 255) / 256, 256>>>(
            W1 + (size_t)l * HD * W1_LD, W1_LD, 128, 256 * 128, nullptr,
            W1p + (size_t)l * 256 * 128);
        pack_kernel<<<(256 * 256 + 255) / 256, 256>>>(
            W2 + (size_t)l * HD * W2_LD, W2_LD, 256, 256 * 256, nullptr,
            W2p + (size_t)l * 256 * 256);
    }
    pack_kernel<<<(256 * 128 + 255) / 256, 256>>>(
        Wh1, HD, 128, 256 * 128, nullptr, Wh1p);

    dim3 ggrid(HD / BN, (NN + BM - 1) / BM);   // (4, 782)
    uint2* hcur = hPkA;
    uint2* hnext = hPkB;

    for (int l = 0; l < NL; l++) {
        const float* W1l = W1 + (size_t)l * HD * W1_LD;
        const float* b2l = b2 + (size_t)l * HD;

        // P = h @ W1[:, :256]^T  (fp32 out, consumed by edge kernel)
        mma_gemm_kernel<<<ggrid, 256>>>(hcur, HD, nullptr, 0,
                                        W1p + (size_t)l * 256 * 128,
                                        nullptr, P, nullptr, NN, HD, 0);

        zero_kernel<<<2048, 256>>>((float4*)hN, NN * HD / 4);

        // hN[dst] += leaky_relu(P[src] + w @ W1[:, 256:259]^T)
        edge_kernel<<<(NE * 32 + 255) / 256, 256>>>(src, dst, w, P, W1l + HD, hN);

        // hNp = pack(hN * invdeg)
        pack_kernel<<<(NN * HP + 255) / 256, 256>>>(hN, HD, HP, NN * HP, invdeg, hNp);

        // h' = relu([h | hN*invdeg] @ W2^T + b2)  -> packed
        mma_gemm_kernel<<<ggrid, 256>>>(hcur, HD, hNp, HD,
                                        W2p + (size_t)l * 256 * 256,
                                        b2l, nullptr, hnext, NN, HD, 1);

        uint2* t = hcur; hcur = hnext; hnext = t;
    }

    // head: x = relu(h @ Wh1^T + bh1) (fp32); out = x @ Wh2^T + bh2
    mma_gemm_kernel<<<ggrid, 256>>>(hcur, HD, nullptr, 0, Wh1p,
                                    bh1, P, nullptr, NN, HD, 1);
    head_dot_kernel<<<(NN * 32 + 255) / 256, 256>>>(P, Wh2, bh2, out);
}